// round 13
// baseline (speedup 1.0000x reference)
#include <cuda_runtime.h>
#include <cuda_fp16.h>
#include <cstdint>

// ===========================================================================
// PackedSirenExperts via mma.sync m16n8k16 fp16 (portable PTX, compute_103).
// R13 = R12 (8 warps, 64x32 warp tiles, single-pass fp16) with B operands
// loaded DIRECTLY from L2 via LDG.128 (lane-contiguous fragment blob),
// depth-2 register pipeline -> B never touches shared memory:
//   crossbar/layer/CTA drops ~420KB -> ~290KB (A-ldsm + A-epilogue only),
//   no cp.async / wait_group / syncwarp in the mainloop.
// CTA = (expert, 64 rows), 256 thr; 2 CTAs/SM (~50 KB smem, ~120 regs).
// ===========================================================================

namespace {
constexpr int Mexp = 64;
constexpr int Bdim = 8192;
constexpr float W0F = 30.0f;

constexpr int OFF_A    = 0;          // 64 rows x 512B swizzled fp16 (32K)
constexpr int OFF_W0   = 32768;      // 768 f
constexpr int OFF_WF   = 35840;      // 768 f
constexpr int OFF_B0   = 38912;      // 256 f
constexpr int OFF_B123 = 39936;      // 768 f
constexpr int OFF_X    = 43008;      // 192 f
constexpr int OFF_PBUF = 43776;      // 1536 f (8 eighths x 64 rows x 3)
constexpr int SMEM_TOTAL = 49920;
}

// prepped weights: slab blob = [m][layer*16 + s] of 8KB:
//   [wn(8 eighths)][lane(32)][32B], lane = rl*4 + q, 32B = 4 n-fragments:
//   +n*8: {W(o=wn*32+n*8+rl, k=2q,2q+1), W(same o, k=2q+8,2q+9)}  (fp16)
__device__ __align__(16) unsigned char g_wp[(size_t)Mexp * 48 * 8192];

// ---------------------------------------------------------------------------
__device__ __forceinline__ uint32_t smem_u32(const void* p) {
    uint32_t a;
    asm("{ .reg .u64 t; cvta.to.shared.u64 t, %1; cvt.u32.u64 %0, t; }" : "=r"(a) : "l"(p));
    return a;
}
__device__ __forceinline__ uint32_t pack2h(float v0, float v1) {
    __half2 t = __floats2half2_rn(v0, v1);
    return *reinterpret_cast<uint32_t*>(&t);
}
// A swizzled byte offset: row r (0..63), col k (0..255) fp16
__device__ __forceinline__ uint32_t aoff(int r, int k) {
    return (uint32_t)(r * 512 + ((((k >> 3) ^ (r & 7)) << 4) | ((k & 7) * 2)));
}
__device__ __forceinline__ void mma16816(float* d, const uint32_t* a,
                                         uint32_t b0, uint32_t b1) {
    asm volatile(
        "mma.sync.aligned.m16n8k16.row.col.f32.f16.f16.f32 "
        "{%0,%1,%2,%3}, {%4,%5,%6,%7}, {%8,%9}, {%0,%1,%2,%3};"
        : "+f"(d[0]), "+f"(d[1]), "+f"(d[2]), "+f"(d[3])
        : "r"(a[0]), "r"(a[1]), "r"(a[2]), "r"(a[3]), "r"(b0), "r"(b1));
}
__device__ __forceinline__ void ldsm4(uint32_t* r, uint32_t addr) {
    asm volatile("ldmatrix.sync.aligned.m8n8.x4.shared.b16 {%0,%1,%2,%3}, [%4];"
                 : "=r"(r[0]), "=r"(r[1]), "=r"(r[2]), "=r"(r[3]) : "r"(addr));
}

// ---------------------------------------------------------------------------
// Prep: fp32 W[m][o][i] -> lane-contiguous fragment blobs (8KB per k16 slab).
// One thread per (m, slab, o); writes 4 8B fragments (one per q) scattered.
// ---------------------------------------------------------------------------
__global__ void prep_weights(const float* __restrict__ w, int layer) {
    int id = blockIdx.x * blockDim.x + threadIdx.x;   // 262144
    int o = id & 255;
    int s = (id >> 8) & 15;
    int m = id >> 12;
    const float* src = w + ((size_t)m * 256 + o) * 256 + s * 16;
    int wn = o >> 5;
    int oo = o & 31;
    int n  = oo >> 3;
    int rl = oo & 7;
    unsigned char* base = g_wp + (size_t)(m * 48 + layer * 16 + s) * 8192
                        + wn * 1024 + n * 8;
#pragma unroll
    for (int q = 0; q < 4; q++) {
        uint2 v;
        v.x = pack2h(src[2 * q],     src[2 * q + 1]);
        v.y = pack2h(src[2 * q + 8], src[2 * q + 9]);
        *reinterpret_cast<uint2*>(base + (rl * 4 + q) * 32) = v;
    }
}

// ---------------------------------------------------------------------------
// Main kernel. grid = Mexp*128 = 8192 CTAs (expert-major), 256 threads.
// ---------------------------------------------------------------------------
__global__ void __launch_bounds__(256, 2)
siren_mma(const float* __restrict__ x,
          const float* __restrict__ w0, const float* __restrict__ b0,
          const float* __restrict__ b1, const float* __restrict__ b2,
          const float* __restrict__ b3,
          const float* __restrict__ wf, const float* __restrict__ bf,
          float* __restrict__ out) {
    extern __shared__ __align__(16) unsigned char smem[];
    const uint32_t sb = smem_u32(smem);
    float* w0s  = reinterpret_cast<float*>(smem + OFF_W0);
    float* wfs  = reinterpret_cast<float*>(smem + OFF_WF);
    float* b0s  = reinterpret_cast<float*>(smem + OFF_B0);
    float* b123 = reinterpret_cast<float*>(smem + OFF_B123);
    float* xs   = reinterpret_cast<float*>(smem + OFF_X);
    float* pbuf = reinterpret_cast<float*>(smem + OFF_PBUF);

    const int tid  = threadIdx.x;
    const int lane = tid & 31;
    const int wn   = tid >> 5;         // warp = n-eighth: cols wn*32..+31
    const int rl   = lane >> 2;        // 0..7
    const int q    = lane & 3;         // 0..3
    const int m    = blockIdx.x >> 7;
    const int bt   = blockIdx.x & 127;
    const int row0 = bt * 64;
    const int lrow  = lane & 15;
    const int lhalf = lane >> 4;

    // per-lane B fragment pointer (32B per slab, slabs 8KB apart)
    const unsigned char* wq = g_wp + (size_t)m * 48 * 8192 + wn * 1024 + lane * 32;

    // ---- stage small tensors ----
    for (int i = tid; i < 768; i += 256) w0s[i] = w0[m * 768 + i];
    for (int i = tid; i < 768; i += 256) wfs[i] = wf[m * 768 + i];
    if (tid < 256) {
        b0s[tid]        = b0[m * 256 + tid];
        b123[tid]       = b1[m * 256 + tid];
        b123[256 + tid] = b2[m * 256 + tid];
        b123[512 + tid] = b3[m * 256 + tid];
    }
    if (tid < 192) xs[tid] = x[(size_t)row0 * 3 + tid];

    // ---- B pipeline: prefetch slab 0 into registers early ----
    uint4 bc0 = __ldg(reinterpret_cast<const uint4*>(wq));
    uint4 bc1 = __ldg(reinterpret_cast<const uint4*>(wq + 16));
    __syncthreads();

    // ---- layer 0: 8192 (row, col-pair) tasks over 256 threads ----
    {
#pragma unroll 4
        for (int i = 0; i < 32; i++) {
            int pid = i * 256 + tid;
            int r = pid & 63;
            int c = (pid >> 6) * 2;
            float x0 = xs[r * 3], x1 = xs[r * 3 + 1], x2 = xs[r * 3 + 2];
            float p0 = fmaf(x2, w0s[c * 3 + 2], fmaf(x1, w0s[c * 3 + 1],
                       fmaf(x0, w0s[c * 3 + 0], b0s[c])));
            float p1 = fmaf(x2, w0s[c * 3 + 5], fmaf(x1, w0s[c * 3 + 4],
                       fmaf(x0, w0s[c * 3 + 3], b0s[c + 1])));
            float v0 = __sinf(W0F * p0);
            float v1 = __sinf(W0F * p1);
            *reinterpret_cast<uint32_t*>(smem + OFF_A + aoff(r, c)) = pack2h(v0, v1);
        }
    }
    __syncthreads();

    // ---- 3 hidden layers over 48 k16 weight slabs ----
    int t = 0;
#pragma unroll 1
    for (int L = 0; L < 3; L++) {
        float acc[4][4][4];               // [n][f][v]
#pragma unroll
        for (int n = 0; n < 4; n++)
#pragma unroll
            for (int f = 0; f < 4; f++)
#pragma unroll
                for (int v = 0; v < 4; v++) acc[n][f][v] = 0.0f;

        uint32_t ah[4][4];

#pragma unroll 1
        for (int s = 0; s < 16; s++, t++) {
            // prefetch slab t+1 B fragments (registers, depth-2 pipeline)
            uint4 bn0, bn1;
            if (t < 47) {
                const unsigned char* nsrc = wq + (size_t)(t + 1) * 8192;
                bn0 = __ldg(reinterpret_cast<const uint4*>(nsrc));
                bn1 = __ldg(reinterpret_cast<const uint4*>(nsrc + 16));
            }

            // A fragments: f=0..3 via ldmatrix.x4
            {
                int c3 = s * 2 + lhalf;
#pragma unroll
                for (int f = 0; f < 4; f++) {
                    int row = f * 16 + lrow;
                    uint32_t ad = sb + (uint32_t)(row * 512 + ((c3 ^ (row & 7)) << 4));
                    ldsm4(ah[f], ad);
                }
            }

            // single pass: A * W   (bq0={bc0.x,bc0.y}, bq1={bc0.z,bc0.w},
            //                       bq2={bc1.x,bc1.y}, bq3={bc1.z,bc1.w})
#pragma unroll
            for (int f = 0; f < 4; f++) mma16816(acc[0][f], ah[f], bc0.x, bc0.y);
#pragma unroll
            for (int f = 0; f < 4; f++) mma16816(acc[1][f], ah[f], bc0.z, bc0.w);
#pragma unroll
            for (int f = 0; f < 4; f++) mma16816(acc[2][f], ah[f], bc1.x, bc1.y);
#pragma unroll
            for (int f = 0; f < 4; f++) mma16816(acc[3][f], ah[f], bc1.z, bc1.w);

            bc0 = bn0; bc1 = bn1;
        }

        __syncthreads();   // all warps done reading A before overwrite

        if (L < 2) {
            const float* bl = b123 + L * 256;
#pragma unroll
            for (int n = 0; n < 4; n++) {
#pragma unroll
                for (int f = 0; f < 4; f++) {
                    int r   = f * 16 + rl;
                    int col = wn * 32 + n * 8 + q * 2;
                    float bb0 = bl[col], bb1 = bl[col + 1];
                    float v0 = __sinf(W0F * (acc[n][f][0] + bb0));
                    float v1 = __sinf(W0F * (acc[n][f][1] + bb1));
                    float v2 = __sinf(W0F * (acc[n][f][2] + bb0));
                    float v3 = __sinf(W0F * (acc[n][f][3] + bb1));
                    *reinterpret_cast<uint32_t*>(smem + OFF_A + aoff(r, col))
                        = pack2h(v0, v1);
                    *reinterpret_cast<uint32_t*>(smem + OFF_A + aoff(r + 8, col))
                        = pack2h(v2, v3);
                }
            }
            __syncthreads();   // A writes visible before next-layer reads
        } else {
            // final: sine + wf dot (3 outputs), partial per n-eighth
            const float* bl = b123 + 512;
            float p[8][3];
#pragma unroll
            for (int i = 0; i < 8; i++)
#pragma unroll
                for (int o = 0; o < 3; o++) p[i][o] = 0.0f;
#pragma unroll
            for (int n = 0; n < 4; n++) {
#pragma unroll
                for (int f = 0; f < 4; f++) {
                    int col = wn * 32 + n * 8 + q * 2;
                    float bb0 = bl[col], bb1 = bl[col + 1];
                    float v0 = __sinf(W0F * (acc[n][f][0] + bb0));
                    float v1 = __sinf(W0F * (acc[n][f][1] + bb1));
                    float v2 = __sinf(W0F * (acc[n][f][2] + bb0));
                    float v3 = __sinf(W0F * (acc[n][f][3] + bb1));
#pragma unroll
                    for (int o = 0; o < 3; o++) {
                        float wf0 = wfs[o * 256 + col], wf1 = wfs[o * 256 + col + 1];
                        p[f * 2 + 0][o] = fmaf(v0, wf0, fmaf(v1, wf1, p[f * 2 + 0][o]));
                        p[f * 2 + 1][o] = fmaf(v2, wf0, fmaf(v3, wf1, p[f * 2 + 1][o]));
                    }
                }
            }
#pragma unroll
            for (int i = 0; i < 8; i++)
#pragma unroll
                for (int o = 0; o < 3; o++) {
                    p[i][o] += __shfl_xor_sync(0xffffffffu, p[i][o], 1);
                    p[i][o] += __shfl_xor_sync(0xffffffffu, p[i][o], 2);
                }
            if (q == 0) {
#pragma unroll
                for (int f = 0; f < 4; f++)
#pragma unroll
                    for (int pr = 0; pr < 2; pr++) {
                        int r = f * 16 + pr * 8 + rl;   // 0..63
#pragma unroll
                        for (int o = 0; o < 3; o++)
                            pbuf[wn * 192 + r * 3 + o] = p[f * 2 + pr][o];
                    }
            }
            __syncthreads();
            if (tid < 192) {
                int r = tid / 3, o = tid - r * 3;
                float v = bf[m * 3 + o];
#pragma unroll
                for (int w8 = 0; w8 < 8; w8++) v += pbuf[w8 * 192 + tid];
                out[((size_t)(row0 + r) * Mexp + m) * 3 + o] = v;
            }
        }
    }
}

// ---------------------------------------------------------------------------
extern "C" void kernel_launch(void* const* d_in, const int* in_sizes, int n_in,
                              void* d_out, int out_size) {
    (void)in_sizes; (void)n_in; (void)out_size;
    const float* x  = (const float*)d_in[0];
    const float* w0 = (const float*)d_in[1];
    const float* b0 = (const float*)d_in[2];
    const float* w1 = (const float*)d_in[3];
    const float* b1 = (const float*)d_in[4];
    const float* w2 = (const float*)d_in[5];
    const float* b2 = (const float*)d_in[6];
    const float* w3 = (const float*)d_in[7];
    const float* b3 = (const float*)d_in[8];
    const float* wf = (const float*)d_in[9];
    const float* bf = (const float*)d_in[10];
    float* out = (float*)d_out;

    cudaFuncSetAttribute(siren_mma, cudaFuncAttributeMaxDynamicSharedMemorySize,
                         SMEM_TOTAL);

    prep_weights<<<1024, 256>>>(w1, 0);
    prep_weights<<<1024, 256>>>(w2, 1);
    prep_weights<<<1024, 256>>>(w3, 2);

    siren_mma<<<Mexp * (Bdim / 64), 256, SMEM_TOTAL>>>(
        x, w0, b0, b1, b2, b3, wf, bf, out);
}

// round 14
// speedup vs baseline: 1.5783x; 1.5783x over previous
#include <cuda_runtime.h>
#include <cuda_fp16.h>
#include <cstdint>

// ===========================================================================
// PackedSirenExperts via mma.sync m16n8k16 fp16 (portable PTX, compute_103).
// R14 = R12 (best: 672us) + two serialization cuts:
//   1. A tile DOUBLE-BUFFERED: epilogue writes the other buffer -> no WAR
//      hazard -> one barrier per layer (was 2); warps start epilogue
//      immediately after their own MMAs.
//   2. Biases/first-layer weights prescaled by 30: sin(fma(30,acc,b30)) --
//      one FMA per sine instead of FADD+FMUL.
// Single-pass fp16 MMA (rel_err ~6e-4), 8 warps, warp tile 64x32,
// warp-private B staging (cp.async, no per-slab CTA barriers).
// CTA = (expert, 64 rows), 256 thr; 2 CTAs/SM (~99 KB smem).
// ===========================================================================

namespace {
constexpr int Mexp = 64;
constexpr int Bdim = 8192;
constexpr float W0F = 30.0f;

constexpr int OFF_A    = 0;          // 2 x (64 rows x 512B swizzled fp16)
constexpr int OFF_WBUF = 65536;      // 2 x 8192 (double-buffered k16 slab)
constexpr int OFF_W0   = 81920;      // 768 f (prescaled by 30)
constexpr int OFF_WF   = 84992;      // 768 f
constexpr int OFF_B0   = 88064;      // 256 f (prescaled by 30)
constexpr int OFF_B123 = 89088;      // 768 f (prescaled by 30)
constexpr int OFF_X    = 92160;      // 192 f
constexpr int OFF_PBUF = 92928;      // 1536 f
constexpr int SMEM_TOTAL = 99072;
}

// prepped weights: slab blob = [m][layer*16 + s] of 8KB, laid out as
// 8 o-eighths (wn) x 32 o-rows x 32B; row = 4 q-words (uint2):
//   {W(k=2q,2q+1), W(k=2q+8,2q+9)}  (fp16)
__device__ __align__(16) unsigned char g_wp[(size_t)Mexp * 48 * 8192];

// ---------------------------------------------------------------------------
__device__ __forceinline__ uint32_t smem_u32(const void* p) {
    uint32_t a;
    asm("{ .reg .u64 t; cvta.to.shared.u64 t, %1; cvt.u32.u64 %0, t; }" : "=r"(a) : "l"(p));
    return a;
}
__device__ __forceinline__ void cp16(uint32_t s, const void* g) {
    asm volatile("cp.async.cg.shared.global [%0], [%1], 16;" :: "r"(s), "l"(g));
}
__device__ __forceinline__ void cp_commit() { asm volatile("cp.async.commit_group;"); }
__device__ __forceinline__ void cp_wait0() {
    asm volatile("cp.async.wait_group 0;" ::: "memory");
}
__device__ __forceinline__ uint32_t pack2h(float v0, float v1) {
    __half2 t = __floats2half2_rn(v0, v1);
    return *reinterpret_cast<uint32_t*>(&t);
}
// A swizzled byte offset: row r (0..63), col k (0..255) fp16
__device__ __forceinline__ uint32_t aoff(int r, int k) {
    return (uint32_t)(r * 512 + ((((k >> 3) ^ (r & 7)) << 4) | ((k & 7) * 2)));
}
__device__ __forceinline__ void mma16816(float* d, const uint32_t* a,
                                         uint32_t b0, uint32_t b1) {
    asm volatile(
        "mma.sync.aligned.m16n8k16.row.col.f32.f16.f16.f32 "
        "{%0,%1,%2,%3}, {%4,%5,%6,%7}, {%8,%9}, {%0,%1,%2,%3};"
        : "+f"(d[0]), "+f"(d[1]), "+f"(d[2]), "+f"(d[3])
        : "r"(a[0]), "r"(a[1]), "r"(a[2]), "r"(a[3]), "r"(b0), "r"(b1));
}
__device__ __forceinline__ void ldsm4(uint32_t* r, uint32_t addr) {
    asm volatile("ldmatrix.sync.aligned.m8n8.x4.shared.b16 {%0,%1,%2,%3}, [%4];"
                 : "=r"(r[0]), "=r"(r[1]), "=r"(r[2]), "=r"(r[3]) : "r"(addr));
}

// ---------------------------------------------------------------------------
// Prep: fp32 W[m][o][i] -> k16-slab blobs (8KB), eighth-major, 32B rows.
// ---------------------------------------------------------------------------
__global__ void prep_weights(const float* __restrict__ w, int layer) {
    int id = blockIdx.x * blockDim.x + threadIdx.x;   // 262144
    int o = id & 255;
    int s = (id >> 8) & 15;
    int m = id >> 12;
    const float* src = w + ((size_t)m * 256 + o) * 256 + s * 16;
    unsigned char* dst = g_wp + (size_t)(m * 48 + layer * 16 + s) * 8192
                       + (o >> 5) * 1024 + (o & 31) * 32;
#pragma unroll
    for (int q = 0; q < 4; q++) {
        uint2 v;
        v.x = pack2h(src[2 * q],     src[2 * q + 1]);
        v.y = pack2h(src[2 * q + 8], src[2 * q + 9]);
        *reinterpret_cast<uint2*>(dst + q * 8) = v;
    }
}

// ---------------------------------------------------------------------------
// Main kernel. grid = Mexp*128 = 8192 CTAs (expert-major), 256 threads.
// ---------------------------------------------------------------------------
__global__ void __launch_bounds__(256, 2)
siren_mma(const float* __restrict__ x,
          const float* __restrict__ w0, const float* __restrict__ b0,
          const float* __restrict__ b1, const float* __restrict__ b2,
          const float* __restrict__ b3,
          const float* __restrict__ wf, const float* __restrict__ bf,
          float* __restrict__ out) {
    extern __shared__ __align__(16) unsigned char smem[];
    const uint32_t sb = smem_u32(smem);
    float* w0s  = reinterpret_cast<float*>(smem + OFF_W0);
    float* wfs  = reinterpret_cast<float*>(smem + OFF_WF);
    float* b0s  = reinterpret_cast<float*>(smem + OFF_B0);
    float* b123 = reinterpret_cast<float*>(smem + OFF_B123);
    float* xs   = reinterpret_cast<float*>(smem + OFF_X);
    float* pbuf = reinterpret_cast<float*>(smem + OFF_PBUF);

    const int tid  = threadIdx.x;
    const int lane = tid & 31;
    const int wn   = tid >> 5;         // warp = n-eighth: cols wn*32..+31
    const int rl   = lane >> 2;        // 0..7
    const int q    = lane & 3;         // 0..3
    const int m    = blockIdx.x >> 7;
    const int bt   = blockIdx.x & 127;
    const int row0 = bt * 64;
    const int lrow  = lane & 15;
    const int lhalf = lane >> 4;

    const unsigned char* wpm = g_wp + (size_t)m * 48 * 8192;

    // ---- prefetch slab 0 (own warp eighth: 1KB) ----
    {
        uint32_t dst = sb + OFF_WBUF + (uint32_t)(wn * 1024 + lane * 16);
        const unsigned char* src = wpm + wn * 1024 + lane * 16;
        cp16(dst, src);
        cp16(dst + 512, src + 512);
        cp_commit();
    }

    // ---- stage small tensors (w0/b0/b123 prescaled by 30) ----
    for (int i = tid; i < 768; i += 256) w0s[i] = W0F * w0[m * 768 + i];
    for (int i = tid; i < 768; i += 256) wfs[i] = wf[m * 768 + i];
    if (tid < 256) {
        b0s[tid]        = W0F * b0[m * 256 + tid];
        b123[tid]       = W0F * b1[m * 256 + tid];
        b123[256 + tid] = W0F * b2[m * 256 + tid];
        b123[512 + tid] = W0F * b3[m * 256 + tid];
    }
    if (tid < 192) xs[tid] = x[(size_t)row0 * 3 + tid];
    __syncthreads();

    // ---- layer 0: writes A buffer 0 ----
    {
#pragma unroll 4
        for (int i = 0; i < 32; i++) {
            int pid = i * 256 + tid;
            int r = pid & 63;
            int c = (pid >> 6) * 2;
            float x0 = xs[r * 3], x1 = xs[r * 3 + 1], x2 = xs[r * 3 + 2];
            float p0 = fmaf(x2, w0s[c * 3 + 2], fmaf(x1, w0s[c * 3 + 1],
                       fmaf(x0, w0s[c * 3 + 0], b0s[c])));
            float p1 = fmaf(x2, w0s[c * 3 + 5], fmaf(x1, w0s[c * 3 + 4],
                       fmaf(x0, w0s[c * 3 + 3], b0s[c + 1])));
            float v0 = __sinf(p0);
            float v1 = __sinf(p1);
            *reinterpret_cast<uint32_t*>(smem + OFF_A + aoff(r, c)) = pack2h(v0, v1);
        }
    }
    __syncthreads();

    // ---- 3 hidden layers; A ping-pongs between buffers 0/1 ----
    int t = 0;
#pragma unroll 1
    for (int L = 0; L < 3; L++) {
        const uint32_t rbase = sb + OFF_A + (uint32_t)((L & 1) ? 32768 : 0);
        const uint32_t wbase = sb + OFF_A + (uint32_t)((L & 1) ? 0 : 32768);

        float acc[4][4][4];               // [n][f][v]
#pragma unroll
        for (int n = 0; n < 4; n++)
#pragma unroll
            for (int f = 0; f < 4; f++)
#pragma unroll
                for (int v = 0; v < 4; v++) acc[n][f][v] = 0.0f;

        uint32_t ah[4][4];

#pragma unroll 1
        for (int s = 0; s < 16; s++, t++) {
            cp_wait0();
            __syncwarp();
            if (t < 47) {
                uint32_t dst = sb + OFF_WBUF + ((t + 1) & 1) * 8192
                             + (uint32_t)(wn * 1024 + lane * 16);
                const unsigned char* src = wpm + (size_t)(t + 1) * 8192
                                         + wn * 1024 + lane * 16;
                cp16(dst, src);
                cp16(dst + 512, src + 512);
                cp_commit();
            }
            const unsigned char* wb = smem + OFF_WBUF + (t & 1) * 8192 + wn * 1024;

            // B fragments: 4 x LDS.64 {W.x, W.y}, 32B rows (conflict-free)
            uint2 bq[4];
#pragma unroll
            for (int n = 0; n < 4; n++)
                bq[n] = *reinterpret_cast<const uint2*>(wb + (n * 8 + rl) * 32 + q * 8);

            // A fragments: f=0..3 via ldmatrix.x4 (from read buffer)
            {
                int c3 = s * 2 + lhalf;
#pragma unroll
                for (int f = 0; f < 4; f++) {
                    int row = f * 16 + lrow;
                    uint32_t ad = rbase + (uint32_t)(row * 512 + ((c3 ^ (row & 7)) << 4));
                    ldsm4(ah[f], ad);
                }
            }

            // single pass: A * W
#pragma unroll
            for (int n = 0; n < 4; n++)
#pragma unroll
                for (int f = 0; f < 4; f++)
                    mma16816(acc[n][f], ah[f], bq[n].x, bq[n].y);
        }

        // NO barrier here: epilogue writes the OTHER A buffer (no WAR hazard)

        if (L < 2) {
            const float* bl = b123 + L * 256;
#pragma unroll
            for (int n = 0; n < 4; n++) {
#pragma unroll
                for (int f = 0; f < 4; f++) {
                    int r   = f * 16 + rl;
                    int col = wn * 32 + n * 8 + q * 2;
                    float bb0 = bl[col], bb1 = bl[col + 1];
                    float v0 = __sinf(fmaf(W0F, acc[n][f][0], bb0));
                    float v1 = __sinf(fmaf(W0F, acc[n][f][1], bb1));
                    float v2 = __sinf(fmaf(W0F, acc[n][f][2], bb0));
                    float v3 = __sinf(fmaf(W0F, acc[n][f][3], bb1));
                    *reinterpret_cast<uint32_t*>(wbase + aoff(r, col) - sb + smem)
                        = pack2h(v0, v1);
                    *reinterpret_cast<uint32_t*>(wbase + aoff(r + 8, col) - sb + smem)
                        = pack2h(v2, v3);
                }
            }
            __syncthreads();   // A writes visible before next-layer reads
        } else {
            // final: sine + wf dot (3 outputs), partial per n-eighth
            const float* bl = b123 + 512;
            float p[8][3];
#pragma unroll
            for (int i = 0; i < 8; i++)
#pragma unroll
                for (int o = 0; o < 3; o++) p[i][o] = 0.0f;
#pragma unroll
            for (int n = 0; n < 4; n++) {
#pragma unroll
                for (int f = 0; f < 4; f++) {
                    int col = wn * 32 + n * 8 + q * 2;
                    float bb0 = bl[col], bb1 = bl[col + 1];
                    float v0 = __sinf(fmaf(W0F, acc[n][f][0], bb0));
                    float v1 = __sinf(fmaf(W0F, acc[n][f][1], bb1));
                    float v2 = __sinf(fmaf(W0F, acc[n][f][2], bb0));
                    float v3 = __sinf(fmaf(W0F, acc[n][f][3], bb1));
#pragma unroll
                    for (int o = 0; o < 3; o++) {
                        float wf0 = wfs[o * 256 + col], wf1 = wfs[o * 256 + col + 1];
                        p[f * 2 + 0][o] = fmaf(v0, wf0, fmaf(v1, wf1, p[f * 2 + 0][o]));
                        p[f * 2 + 1][o] = fmaf(v2, wf0, fmaf(v3, wf1, p[f * 2 + 1][o]));
                    }
                }
            }
#pragma unroll
            for (int i = 0; i < 8; i++)
#pragma unroll
                for (int o = 0; o < 3; o++) {
                    p[i][o] += __shfl_xor_sync(0xffffffffu, p[i][o], 1);
                    p[i][o] += __shfl_xor_sync(0xffffffffu, p[i][o], 2);
                }
            if (q == 0) {
#pragma unroll
                for (int f = 0; f < 4; f++)
#pragma unroll
                    for (int pr = 0; pr < 2; pr++) {
                        int r = f * 16 + pr * 8 + rl;   // 0..63
#pragma unroll
                        for (int o = 0; o < 3; o++)
                            pbuf[wn * 192 + r * 3 + o] = p[f * 2 + pr][o];
                    }
            }
            __syncthreads();
            if (tid < 192) {
                int r = tid / 3, o = tid - r * 3;
                float v = bf[m * 3 + o];
#pragma unroll
                for (int w8 = 0; w8 < 8; w8++) v += pbuf[w8 * 192 + tid];
                out[((size_t)(row0 + r) * Mexp + m) * 3 + o] = v;
            }
        }
    }
}

// ---------------------------------------------------------------------------
extern "C" void kernel_launch(void* const* d_in, const int* in_sizes, int n_in,
                              void* d_out, int out_size) {
    (void)in_sizes; (void)n_in; (void)out_size;
    const float* x  = (const float*)d_in[0];
    const float* w0 = (const float*)d_in[1];
    const float* b0 = (const float*)d_in[2];
    const float* w1 = (const float*)d_in[3];
    const float* b1 = (const float*)d_in[4];
    const float* w2 = (const float*)d_in[5];
    const float* b2 = (const float*)d_in[6];
    const float* w3 = (const float*)d_in[7];
    const float* b3 = (const float*)d_in[8];
    const float* wf = (const float*)d_in[9];
    const float* bf = (const float*)d_in[10];
    float* out = (float*)d_out;

    cudaFuncSetAttribute(siren_mma, cudaFuncAttributeMaxDynamicSharedMemorySize,
                         SMEM_TOTAL);

    prep_weights<<<1024, 256>>>(w1, 0);
    prep_weights<<<1024, 256>>>(w2, 1);
    prep_weights<<<1024, 256>>>(w3, 2);

    siren_mma<<<Mexp * (Bdim / 64), 256, SMEM_TOTAL>>>(
        x, w0, b0, b1, b2, b3, wf, bf, out);
}